// round 1
// baseline (speedup 1.0000x reference)
#include <cuda_runtime.h>
#include <math.h>

#define FULLMASK 0xffffffffu

namespace {
constexpr int Bc = 16, Tc = 12, Nc = 2000, Ec = 8000;
constexpr int Mc = Bc * Nc;          // 32000
constexpr int ETOT = Bc * Ec + Mc;   // 160000 (edges + self loops)
constexpr int Dc = 64, FFc = 128, NHc = 4, Lc = 2;
constexpr int ROWS = Tc * Mc;        // 384000
}

// ---------------- scratch (static device memory; no allocation) ----------------
__device__ float g_seq[ROWS * Dc];        // [T,M,64]
__device__ float g_qkv[ROWS * 3 * Dc];    // [T,M,192]
__device__ float g_o[ROWS * Dc];          // [T,M,64]
__device__ float g_ff[ROWS * FFc];        // [T,M,128]
__device__ float g_h2[ROWS * Dc];         // GAT2 pre-agg features
__device__ float g_r1[ROWS * 4];          // GAT1 per-head aggregated scalar
__device__ float g_as2[ROWS * 4];
__device__ float g_ad2[ROWS * 4];
__device__ int   g_cnt[Mc];
__device__ int   g_off[Mc + 1];
__device__ int   g_cur[Mc];
__device__ int   g_csrc[ETOT];
__device__ float g_S1[4], g_D1[4];

// ---------------- CSR build ----------------
__global__ void k_init(const float* __restrict__ W1, const float* __restrict__ as1,
                       const float* __restrict__ ad1) {
  int i = blockIdx.x * blockDim.x + threadIdx.x;
  if (i < Mc) g_cnt[i] = 0;
  if (i < 4) {
    float s = 0.f, d = 0.f;
    for (int c = 0; c < 8; c++) { s += W1[i * 8 + c] * as1[i * 8 + c];
                                  d += W1[i * 8 + c] * ad1[i * 8 + c]; }
    g_S1[i] = s; g_D1[i] = d;
  }
}

__global__ void k_hist(const int* __restrict__ ei) {
  int i = blockIdx.x * blockDim.x + threadIdx.x;
  if (i >= ETOT) return;
  int dst;
  if (i < Bc * Ec) { int b = i / Ec, e = i - b * Ec; dst = ei[Ec + e] + b * Nc; }
  else dst = i - Bc * Ec;
  atomicAdd(&g_cnt[dst], 1);
}

__global__ void k_scan() {
  __shared__ int sh[1024];
  const int CH = 32;  // 1024*32 = 32768 >= Mc
  int t = threadIdx.x;
  int base = t * CH;
  int s = 0;
  for (int i = 0; i < CH; i++) { int idx = base + i; if (idx < Mc) s += g_cnt[idx]; }
  sh[t] = s; __syncthreads();
  for (int o = 1; o < 1024; o <<= 1) {
    int v = (t >= o) ? sh[t - o] : 0;
    __syncthreads();
    sh[t] += v;
    __syncthreads();
  }
  int run = (t == 0) ? 0 : sh[t - 1];
  for (int i = 0; i < CH; i++) {
    int idx = base + i;
    if (idx <= Mc) g_off[idx] = run;
    if (idx < Mc) { g_cur[idx] = run; run += g_cnt[idx]; }
  }
}

__global__ void k_scatter(const int* __restrict__ ei) {
  int i = blockIdx.x * blockDim.x + threadIdx.x;
  if (i >= ETOT) return;
  int src, dst;
  if (i < Bc * Ec) { int b = i / Ec, e = i - b * Ec;
                     src = ei[e] + b * Nc; dst = ei[Ec + e] + b * Nc; }
  else { src = dst = i - Bc * Ec; }
  int p = atomicAdd(&g_cur[dst], 1);
  g_csrc[p] = src;
}

// ---------------- GAT layer 1 (factorized: scalar input) ----------------
__global__ void k_gat1(const float* __restrict__ x) {
  int idx = blockIdx.x * blockDim.x + threadIdx.x;
  if (idx >= ROWS) return;
  int t = idx / Mc, m = idx - t * Mc;
  int b = m / Nc, n = m - b * Nc;
  float xd = x[(b * Tc + t) * Nc + n];
  float S[4], Dd[4];
#pragma unroll
  for (int h = 0; h < 4; h++) { S[h] = g_S1[h]; Dd[h] = g_D1[h]; }
  int j0 = g_off[m], j1 = g_off[m + 1];
  float mx[4] = {-1e30f, -1e30f, -1e30f, -1e30f};
  for (int j = j0; j < j1; j++) {
    int s = g_csrc[j]; int bs = s / Nc, ns = s - bs * Nc;
    float xs = x[(bs * Tc + t) * Nc + ns];
#pragma unroll
    for (int h = 0; h < 4; h++) {
      float e = xs * S[h] + xd * Dd[h];
      e = fmaxf(e, 0.2f * e);                 // leaky_relu(., 0.2)
      mx[h] = fmaxf(mx[h], e);
    }
  }
  float sw[4] = {0, 0, 0, 0}, swx[4] = {0, 0, 0, 0};
  for (int j = j0; j < j1; j++) {
    int s = g_csrc[j]; int bs = s / Nc, ns = s - bs * Nc;
    float xs = x[(bs * Tc + t) * Nc + ns];
#pragma unroll
    for (int h = 0; h < 4; h++) {
      float e = xs * S[h] + xd * Dd[h];
      e = fmaxf(e, 0.2f * e);
      float w = expf(e - mx[h]);
      sw[h] += w; swx[h] += w * xs;
    }
  }
#pragma unroll
  for (int h = 0; h < 4; h++) g_r1[idx * 4 + h] = swx[h] / (sw[h] + 1e-16f);
}

// ---------------- GAT2: feature transform + attention logits ----------------
__global__ void k_gat2pre(const float* __restrict__ W1, const float* __restrict__ b1,
                          const float* __restrict__ W2, const float* __restrict__ aw,
                          const float* __restrict__ dw) {
  __shared__ float W2s[32 * 64];
  __shared__ float W1s[32], b1s[32], aws[64], dws[64];
  for (int i = threadIdx.x; i < 2048; i += blockDim.x) W2s[i] = W2[i];
  if (threadIdx.x < 32) { W1s[threadIdx.x] = W1[threadIdx.x]; b1s[threadIdx.x] = b1[threadIdx.x]; }
  if (threadIdx.x < 64) { aws[threadIdx.x] = aw[threadIdx.x]; dws[threadIdx.x] = dw[threadIdx.x]; }
  __syncthreads();
  int idx = blockIdx.x * blockDim.x + threadIdx.x;
  if (idx >= ROWS) return;
  float r[4];
#pragma unroll
  for (int h = 0; h < 4; h++) r[h] = g_r1[idx * 4 + h];
  float acc[64];
#pragma unroll
  for (int j = 0; j < 64; j++) acc[j] = 0.f;
  const float4* W2v = (const float4*)W2s;
#pragma unroll
  for (int hc = 0; hc < 32; hc++) {
    float v = fmaxf(fmaf(W1s[hc], r[hc >> 3], b1s[hc]), 0.f);  // relu(GAT1 out)
#pragma unroll
    for (int q = 0; q < 16; q++) {
      float4 w = W2v[hc * 16 + q];
      acc[q * 4 + 0] = fmaf(v, w.x, acc[q * 4 + 0]);
      acc[q * 4 + 1] = fmaf(v, w.y, acc[q * 4 + 1]);
      acc[q * 4 + 2] = fmaf(v, w.z, acc[q * 4 + 2]);
      acc[q * 4 + 3] = fmaf(v, w.w, acc[q * 4 + 3]);
    }
  }
  float4* outv = (float4*)&g_h2[idx * 64];
#pragma unroll
  for (int q = 0; q < 16; q++)
    outv[q] = make_float4(acc[q * 4], acc[q * 4 + 1], acc[q * 4 + 2], acc[q * 4 + 3]);
  float sa[4] = {0, 0, 0, 0}, da[4] = {0, 0, 0, 0};
#pragma unroll
  for (int j = 0; j < 64; j++) {
    int h = j >> 4;
    sa[h] = fmaf(acc[j], aws[j], sa[h]);
    da[h] = fmaf(acc[j], dws[j], da[h]);
  }
#pragma unroll
  for (int h = 0; h < 4; h++) { g_as2[idx * 4 + h] = sa[h]; g_ad2[idx * 4 + h] = da[h]; }
}

// ---------------- GAT2 aggregation + bias + relu + positional encoding ----------------
__device__ __forceinline__ float pe_val(int t, int f) {
  float i2 = (float)(f & ~1);
  float d = expf(i2 * (-9.210340371976184f / 64.f));  // -ln(10000)/D * 2i
  float a = (float)t * d;
  return (f & 1) ? cosf(a) : sinf(a);
}

__global__ void k_gat2agg(const float* __restrict__ b2) {
  int gw = (blockIdx.x * blockDim.x + threadIdx.x) >> 5;
  if (gw >= ROWS) return;
  int lane = threadIdx.x & 31;
  int t = gw / Mc, m = gw - t * Mc;
  int h = lane & 3;                 // head computed by this lane (lanes 0..3 are sources)
  int tbase = t * Mc;
  float adv = g_ad2[gw * 4 + h];
  int j0 = g_off[m], j1 = g_off[m + 1];
  float mx = -1e30f;
  for (int j = j0; j < j1; j++) {
    int s = g_csrc[j];
    float e = g_as2[(tbase + s) * 4 + h] + adv;
    e = fmaxf(e, 0.2f * e);
    mx = fmaxf(mx, e);
  }
  int hA = lane >> 4;           // head of feature f0 = lane      (0 or 1)
  int hB = 2 + (lane >> 4);     // head of feature f1 = lane + 32 (2 or 3)
  float sw = 0.f, acc0 = 0.f, acc1 = 0.f;
  for (int j = j0; j < j1; j++) {
    int s = g_csrc[j];
    float e = g_as2[(tbase + s) * 4 + h] + adv;
    e = fmaxf(e, 0.2f * e);
    float w = expf(e - mx);
    sw += w;
    float wA = __shfl_sync(FULLMASK, w, hA);
    float wB = __shfl_sync(FULLMASK, w, hB);
    const float* hp = g_h2 + (tbase + s) * 64;
    acc0 = fmaf(wA, hp[lane], acc0);
    acc1 = fmaf(wB, hp[lane + 32], acc1);
  }
  float swA = __shfl_sync(FULLMASK, sw, hA);
  float swB = __shfl_sync(FULLMASK, sw, hB);
  float o0 = fmaxf(acc0 / (swA + 1e-16f) + b2[lane], 0.f) + pe_val(t, lane);
  float o1 = fmaxf(acc1 / (swB + 1e-16f) + b2[lane + 32], 0.f) + pe_val(t, lane + 32);
  g_seq[gw * 64 + lane] = o0;
  g_seq[gw * 64 + lane + 32] = o1;
}

// ---------------- generic dense: Y[row, j] = act(sum_i X[row,i]*W[j,i] + b[j]) ----------------
template <int IN, int OUT, bool RELU>
__global__ void k_dense(const float* __restrict__ X, const float* __restrict__ W,
                        const float* __restrict__ bias, float* __restrict__ Y, int ostride) {
  __shared__ float Ws[IN * OUT];  // transposed: Ws[i*OUT + j]
  for (int idx = threadIdx.x; idx < IN * OUT; idx += blockDim.x) {
    int j = idx / IN, i = idx - j * IN;
    Ws[i * OUT + j] = W[idx];
  }
  __syncthreads();
  int lane = threadIdx.x & 31, warp = threadIdx.x >> 5;
  constexpr int R = 4, KI = IN / 32, KO = OUT / 32;
  int row0 = (blockIdx.x * (blockDim.x >> 5) + warp) * R;
  if (row0 >= ROWS) return;
  float xr[R][KI];
#pragma unroll
  for (int r = 0; r < R; r++)
#pragma unroll
    for (int k = 0; k < KI; k++)
      xr[r][k] = X[(row0 + r) * IN + lane + 32 * k];
  float acc[R][KO];
#pragma unroll
  for (int r = 0; r < R; r++)
#pragma unroll
    for (int k = 0; k < KO; k++) acc[r][k] = 0.f;
#pragma unroll
  for (int kk = 0; kk < KI; kk++)
#pragma unroll
    for (int i2 = 0; i2 < 32; i2++) {
      float xi[R];
#pragma unroll
      for (int r = 0; r < R; r++) xi[r] = __shfl_sync(FULLMASK, xr[r][kk], i2);
      int i = kk * 32 + i2;
#pragma unroll
      for (int k = 0; k < KO; k++) {
        float w = Ws[i * OUT + lane + 32 * k];
#pragma unroll
        for (int r = 0; r < R; r++) acc[r][k] = fmaf(xi[r], w, acc[r][k]);
      }
    }
#pragma unroll
  for (int r = 0; r < R; r++)
#pragma unroll
    for (int k = 0; k < KO; k++) {
      int j = lane + 32 * k;
      float y = acc[r][k] + __ldg(&bias[j]);
      if (RELU) y = fmaxf(y, 0.f);
      Y[(row0 + r) * ostride + j] = y;
    }
}

// ---------------- dense(OUT=64) + bias + residual + LayerNorm (in-place on seq) ----------------
template <int IN>
__global__ void k_out_ln(const float* __restrict__ X, const float* __restrict__ W,
                         const float* __restrict__ bias, const float* __restrict__ g,
                         const float* __restrict__ be, float* __restrict__ seq) {
  __shared__ float Ws[IN * 64];
  for (int idx = threadIdx.x; idx < IN * 64; idx += blockDim.x) {
    int j = idx / IN, i = idx - j * IN;
    Ws[i * 64 + j] = W[idx];
  }
  __syncthreads();
  int lane = threadIdx.x & 31, warp = threadIdx.x >> 5;
  constexpr int R = 4, KI = IN / 32;
  int row0 = (blockIdx.x * (blockDim.x >> 5) + warp) * R;
  if (row0 >= ROWS) return;
  float xr[R][KI];
#pragma unroll
  for (int r = 0; r < R; r++)
#pragma unroll
    for (int k = 0; k < KI; k++)
      xr[r][k] = X[(row0 + r) * IN + lane + 32 * k];
  float acc0[R], acc1[R];
#pragma unroll
  for (int r = 0; r < R; r++) { acc0[r] = 0.f; acc1[r] = 0.f; }
#pragma unroll
  for (int kk = 0; kk < KI; kk++)
#pragma unroll
    for (int i2 = 0; i2 < 32; i2++) {
      float xi[R];
#pragma unroll
      for (int r = 0; r < R; r++) xi[r] = __shfl_sync(FULLMASK, xr[r][kk], i2);
      int i = kk * 32 + i2;
      float w0 = Ws[i * 64 + lane];
      float w1 = Ws[i * 64 + lane + 32];
#pragma unroll
      for (int r = 0; r < R; r++) {
        acc0[r] = fmaf(xi[r], w0, acc0[r]);
        acc1[r] = fmaf(xi[r], w1, acc1[r]);
      }
    }
#pragma unroll
  for (int r = 0; r < R; r++) {
    int row = row0 + r;
    float y0 = acc0[r] + __ldg(&bias[lane]) + seq[row * 64 + lane];
    float y1 = acc1[r] + __ldg(&bias[lane + 32]) + seq[row * 64 + lane + 32];
    float s = y0 + y1;
#pragma unroll
    for (int o = 16; o > 0; o >>= 1) s += __shfl_xor_sync(FULLMASK, s, o);
    float mu = s * (1.f / 64.f);
    float d0 = y0 - mu, d1 = y1 - mu;
    float v = d0 * d0 + d1 * d1;
#pragma unroll
    for (int o = 16; o > 0; o >>= 1) v += __shfl_xor_sync(FULLMASK, v, o);
    float rs = rsqrtf(v * (1.f / 64.f) + 1e-5f);
    seq[row * 64 + lane] = fmaf(d0 * rs, __ldg(&g[lane]), __ldg(&be[lane]));
    seq[row * 64 + lane + 32] = fmaf(d1 * rs, __ldg(&g[lane + 32]), __ldg(&be[lane + 32]));
  }
}

// ---------------- attention over T=12 (per node, per head) ----------------
__global__ void k_attn() {
  __shared__ float ks[8][12][16];
  __shared__ float vs[8][12][16];
  int g = threadIdx.x / 12, tt = threadIdx.x - g * 12;
  int mh = blockIdx.x * 8 + g;
  int h = mh & 3, m = mh >> 2;
  const float* kp = g_qkv + (tt * Mc + m) * 192 + 64 + h * 16;
  const float* vp = kp + 64;
#pragma unroll
  for (int i = 0; i < 4; i++) {
    ((float4*)ks[g][tt])[i] = ((const float4*)kp)[i];
    ((float4*)vs[g][tt])[i] = ((const float4*)vp)[i];
  }
  float q[16];
  const float* qp = g_qkv + (tt * Mc + m) * 192 + h * 16;
#pragma unroll
  for (int i = 0; i < 4; i++) ((float4*)q)[i] = ((const float4*)qp)[i];
  __syncthreads();
  float sc[12];
  float mx = -1e30f;
#pragma unroll
  for (int s = 0; s < 12; s++) {
    float d = 0.f;
#pragma unroll
    for (int i = 0; i < 16; i++) d = fmaf(q[i], ks[g][s][i], d);
    d *= 0.25f;  // 1/sqrt(16)
    sc[s] = d; mx = fmaxf(mx, d);
  }
  float sum = 0.f;
#pragma unroll
  for (int s = 0; s < 12; s++) { sc[s] = expf(sc[s] - mx); sum += sc[s]; }
  float inv = 1.f / sum;
  float o[16];
#pragma unroll
  for (int i = 0; i < 16; i++) o[i] = 0.f;
#pragma unroll
  for (int s = 0; s < 12; s++) {
    float a = sc[s] * inv;
#pragma unroll
    for (int i = 0; i < 16; i++) o[i] = fmaf(a, vs[g][s][i], o[i]);
  }
  float* op = g_o + (tt * Mc + m) * 64 + h * 16;
#pragma unroll
  for (int i = 0; i < 4; i++) ((float4*)op)[i] = ((float4*)o)[i];
}

// ---------------- prediction head ----------------
__global__ void k_head(const float* __restrict__ Wh, const float* __restrict__ bh,
                       float* __restrict__ out) {
  int m = blockIdx.x * blockDim.x + threadIdx.x;
  if (m >= Mc) return;
  const float* sp = g_seq + ((Tc - 1) * Mc + m) * 64;
  float a0 = 0.f, a1 = 0.f, a2 = 0.f;
#pragma unroll 8
  for (int d = 0; d < 64; d++) {
    float v = sp[d];
    a0 = fmaf(v, __ldg(&Wh[d]), a0);
    a1 = fmaf(v, __ldg(&Wh[64 + d]), a1);
    a2 = fmaf(v, __ldg(&Wh[128 + d]), a2);
  }
  int b = m / Nc, n = m - b * Nc;
  out[(b * 3 + 0) * Nc + n] = a0 + __ldg(&bh[0]);
  out[(b * 3 + 1) * Nc + n] = a1 + __ldg(&bh[1]);
  out[(b * 3 + 2) * Nc + n] = a2 + __ldg(&bh[2]);
}

// ---------------- launch ----------------
extern "C" void kernel_launch(void* const* d_in, const int* in_sizes, int n_in,
                              void* d_out, int out_size) {
  const float* x    = (const float*)d_in[0];
  const int*   ei   = (const int*)d_in[1];
  const float* W1   = (const float*)d_in[2];
  const float* as1  = (const float*)d_in[3];
  const float* ad1  = (const float*)d_in[4];
  const float* b1   = (const float*)d_in[5];
  const float* W2   = (const float*)d_in[6];
  const float* as2w = (const float*)d_in[7];
  const float* ad2w = (const float*)d_in[8];
  const float* b2   = (const float*)d_in[9];
  const float* Wqkv = (const float*)d_in[10];
  const float* bqkv = (const float*)d_in[11];
  const float* Wo   = (const float*)d_in[12];
  const float* bo   = (const float*)d_in[13];
  const float* Wf1  = (const float*)d_in[14];
  const float* bf1  = (const float*)d_in[15];
  const float* Wf2  = (const float*)d_in[16];
  const float* bf2  = (const float*)d_in[17];
  const float* g1   = (const float*)d_in[18];
  const float* be1  = (const float*)d_in[19];
  const float* g2   = (const float*)d_in[20];
  const float* be2  = (const float*)d_in[21];
  const float* Wh   = (const float*)d_in[22];
  const float* bh   = (const float*)d_in[23];
  float* out = (float*)d_out;

  float *p_seq, *p_qkv, *p_o, *p_ff;
  cudaGetSymbolAddress((void**)&p_seq, g_seq);
  cudaGetSymbolAddress((void**)&p_qkv, g_qkv);
  cudaGetSymbolAddress((void**)&p_o, g_o);
  cudaGetSymbolAddress((void**)&p_ff, g_ff);

  // graph CSR build (per launch; deterministic graph)
  k_init<<<(Mc + 255) / 256, 256>>>(W1, as1, ad1);
  k_hist<<<(ETOT + 255) / 256, 256>>>(ei);
  k_scan<<<1, 1024>>>();
  k_scatter<<<(ETOT + 255) / 256, 256>>>(ei);

  // GNN (all 12 timesteps batched)
  k_gat1<<<(ROWS + 255) / 256, 256>>>(x);
  k_gat2pre<<<(ROWS + 127) / 128, 128>>>(W1, b1, W2, as2w, ad2w);
  k_gat2agg<<<ROWS * 32 / 128, 128>>>(b2);

  // transformer encoder
  const int DBLK = ROWS / 32;  // 256 threads = 8 warps x 4 rows -> 32 rows/block
  for (int l = 0; l < Lc; l++) {
    for (int p = 0; p < 3; p++)
      k_dense<64, 64, false><<<DBLK, 256>>>(p_seq, Wqkv + l * 192 * 64 + p * 64 * 64,
                                            bqkv + l * 192 + p * 64, p_qkv + p * 64, 192);
    k_attn<<<(Mc * NHc) / 8, 96>>>();
    k_out_ln<64><<<DBLK, 256>>>(p_o, Wo + l * 64 * 64, bo + l * 64,
                                g1 + l * 64, be1 + l * 64, p_seq);
    k_dense<64, 128, true><<<DBLK, 256>>>(p_seq, Wf1 + l * 128 * 64, bf1 + l * 128, p_ff, 128);
    k_out_ln<128><<<DBLK, 256>>>(p_ff, Wf2 + l * 64 * 128, bf2 + l * 64,
                                 g2 + l * 64, be2 + l * 64, p_seq);
  }

  k_head<<<(Mc + 255) / 256, 256>>>(Wh, bh, out);
}

// round 2
// speedup vs baseline: 2.3343x; 2.3343x over previous
#include <cuda_runtime.h>
#include <math.h>

#define FULLMASK 0xffffffffu

namespace {
constexpr int Bc = 16, Tc = 12, Nc = 2000, Ec = 8000;
constexpr int Mc = Bc * Nc;          // 32000
constexpr int ETOT = Bc * Ec + Mc;   // 160000 (edges + self loops)
constexpr int Dc = 64, FFc = 128, NHc = 4, Lc = 2;
constexpr int ROWS = Tc * Mc;        // 384000
}

// ---------------- scratch (static device memory; no allocation) ----------------
__device__ float g_seq[ROWS * Dc];        // [T,M,64]
__device__ float g_qkv[ROWS * 3 * Dc];    // [T,M,192]
__device__ float g_o[ROWS * Dc];          // [T,M,64]
__device__ float g_h2[ROWS * Dc];         // GAT2 pre-agg features
__device__ float g_r1[ROWS * 4];          // GAT1 per-head aggregated scalar
__device__ float g_as2[ROWS * 4];
__device__ float g_ad2[ROWS * 4];
__device__ int   g_cnt[Mc];
__device__ int   g_off[Mc + 1];
__device__ int   g_cur[Mc];
__device__ int   g_csrc[ETOT];
__device__ float g_S1[4], g_D1[4];

// ---------------- CSR build ----------------
__global__ void k_init(const float* __restrict__ W1, const float* __restrict__ as1,
                       const float* __restrict__ ad1) {
  int i = blockIdx.x * blockDim.x + threadIdx.x;
  if (i < Mc) g_cnt[i] = 0;
  if (i < 4) {
    float s = 0.f, d = 0.f;
    for (int c = 0; c < 8; c++) { s += W1[i * 8 + c] * as1[i * 8 + c];
                                  d += W1[i * 8 + c] * ad1[i * 8 + c]; }
    g_S1[i] = s; g_D1[i] = d;
  }
}

__global__ void k_hist(const int* __restrict__ ei) {
  int i = blockIdx.x * blockDim.x + threadIdx.x;
  if (i >= ETOT) return;
  int dst;
  if (i < Bc * Ec) { int b = i / Ec, e = i - b * Ec; dst = ei[Ec + e] + b * Nc; }
  else dst = i - Bc * Ec;
  atomicAdd(&g_cnt[dst], 1);
}

__global__ void k_scan() {
  __shared__ int sh[1024];
  const int CH = 32;
  int t = threadIdx.x;
  int base = t * CH;
  int s = 0;
  for (int i = 0; i < CH; i++) { int idx = base + i; if (idx < Mc) s += g_cnt[idx]; }
  sh[t] = s; __syncthreads();
  for (int o = 1; o < 1024; o <<= 1) {
    int v = (t >= o) ? sh[t - o] : 0;
    __syncthreads();
    sh[t] += v;
    __syncthreads();
  }
  int run = (t == 0) ? 0 : sh[t - 1];
  for (int i = 0; i < CH; i++) {
    int idx = base + i;
    if (idx <= Mc) g_off[idx] = run;
    if (idx < Mc) { g_cur[idx] = run; run += g_cnt[idx]; }
  }
}

__global__ void k_scatter(const int* __restrict__ ei) {
  int i = blockIdx.x * blockDim.x + threadIdx.x;
  if (i >= ETOT) return;
  int src, dst;
  if (i < Bc * Ec) { int b = i / Ec, e = i - b * Ec;
                     src = ei[e] + b * Nc; dst = ei[Ec + e] + b * Nc; }
  else { src = dst = i - Bc * Ec; }
  int p = atomicAdd(&g_cur[dst], 1);
  g_csrc[p] = src;
}

// ---------------- GAT layer 1 (factorized: scalar input) ----------------
__global__ void k_gat1(const float* __restrict__ x) {
  int idx = blockIdx.x * blockDim.x + threadIdx.x;
  if (idx >= ROWS) return;
  int t = idx / Mc, m = idx - t * Mc;
  int b = m / Nc, n = m - b * Nc;
  float xd = x[(b * Tc + t) * Nc + n];
  float S[4], Dd[4];
#pragma unroll
  for (int h = 0; h < 4; h++) { S[h] = g_S1[h]; Dd[h] = g_D1[h]; }
  int j0 = g_off[m], j1 = g_off[m + 1];
  float mx[4] = {-1e30f, -1e30f, -1e30f, -1e30f};
  for (int j = j0; j < j1; j++) {
    int s = g_csrc[j]; int bs = s / Nc, ns = s - bs * Nc;
    float xs = x[(bs * Tc + t) * Nc + ns];
#pragma unroll
    for (int h = 0; h < 4; h++) {
      float e = xs * S[h] + xd * Dd[h];
      e = fmaxf(e, 0.2f * e);
      mx[h] = fmaxf(mx[h], e);
    }
  }
  float sw[4] = {0, 0, 0, 0}, swx[4] = {0, 0, 0, 0};
  for (int j = j0; j < j1; j++) {
    int s = g_csrc[j]; int bs = s / Nc, ns = s - bs * Nc;
    float xs = x[(bs * Tc + t) * Nc + ns];
#pragma unroll
    for (int h = 0; h < 4; h++) {
      float e = xs * S[h] + xd * Dd[h];
      e = fmaxf(e, 0.2f * e);
      float w = expf(e - mx[h]);
      sw[h] += w; swx[h] += w * xs;
    }
  }
#pragma unroll
  for (int h = 0; h < 4; h++) g_r1[idx * 4 + h] = swx[h] / (sw[h] + 1e-16f);
}

// ---------------- GAT2: feature transform + attention logits ----------------
__global__ void k_gat2pre(const float* __restrict__ W1, const float* __restrict__ b1,
                          const float* __restrict__ W2, const float* __restrict__ aw,
                          const float* __restrict__ dw) {
  __shared__ float W2s[32 * 64];
  __shared__ float W1s[32], b1s[32], aws[64], dws[64];
  for (int i = threadIdx.x; i < 2048; i += blockDim.x) W2s[i] = W2[i];
  if (threadIdx.x < 32) { W1s[threadIdx.x] = W1[threadIdx.x]; b1s[threadIdx.x] = b1[threadIdx.x]; }
  if (threadIdx.x < 64) { aws[threadIdx.x] = aw[threadIdx.x]; dws[threadIdx.x] = dw[threadIdx.x]; }
  __syncthreads();
  int idx = blockIdx.x * blockDim.x + threadIdx.x;
  if (idx >= ROWS) return;
  float r[4];
#pragma unroll
  for (int h = 0; h < 4; h++) r[h] = g_r1[idx * 4 + h];
  float acc[64];
#pragma unroll
  for (int j = 0; j < 64; j++) acc[j] = 0.f;
  const float4* W2v = (const float4*)W2s;
#pragma unroll
  for (int hc = 0; hc < 32; hc++) {
    float v = fmaxf(fmaf(W1s[hc], r[hc >> 3], b1s[hc]), 0.f);
#pragma unroll
    for (int q = 0; q < 16; q++) {
      float4 w = W2v[hc * 16 + q];
      acc[q * 4 + 0] = fmaf(v, w.x, acc[q * 4 + 0]);
      acc[q * 4 + 1] = fmaf(v, w.y, acc[q * 4 + 1]);
      acc[q * 4 + 2] = fmaf(v, w.z, acc[q * 4 + 2]);
      acc[q * 4 + 3] = fmaf(v, w.w, acc[q * 4 + 3]);
    }
  }
  float4* outv = (float4*)&g_h2[idx * 64];
#pragma unroll
  for (int q = 0; q < 16; q++)
    outv[q] = make_float4(acc[q * 4], acc[q * 4 + 1], acc[q * 4 + 2], acc[q * 4 + 3]);
  float sa[4] = {0, 0, 0, 0}, da[4] = {0, 0, 0, 0};
#pragma unroll
  for (int j = 0; j < 64; j++) {
    int h = j >> 4;
    sa[h] = fmaf(acc[j], aws[j], sa[h]);
    da[h] = fmaf(acc[j], dws[j], da[h]);
  }
#pragma unroll
  for (int h = 0; h < 4; h++) { g_as2[idx * 4 + h] = sa[h]; g_ad2[idx * 4 + h] = da[h]; }
}

// ---------------- GAT2 aggregation + bias + relu + positional encoding ----------------
__device__ __forceinline__ float pe_val(int t, int f) {
  float i2 = (float)(f & ~1);
  float d = expf(i2 * (-9.210340371976184f / 64.f));
  float a = (float)t * d;
  return (f & 1) ? cosf(a) : sinf(a);
}

__global__ void k_gat2agg(const float* __restrict__ b2) {
  int gw = (blockIdx.x * blockDim.x + threadIdx.x) >> 5;
  if (gw >= ROWS) return;
  int lane = threadIdx.x & 31;
  int t = gw / Mc, m = gw - t * Mc;
  int h = lane & 3;
  int tbase = t * Mc;
  float adv = g_ad2[gw * 4 + h];
  int j0 = g_off[m], j1 = g_off[m + 1];
  float mx = -1e30f;
  for (int j = j0; j < j1; j++) {
    int s = g_csrc[j];
    float e = g_as2[(tbase + s) * 4 + h] + adv;
    e = fmaxf(e, 0.2f * e);
    mx = fmaxf(mx, e);
  }
  int hA = lane >> 4;
  int hB = 2 + (lane >> 4);
  float sw = 0.f, acc0 = 0.f, acc1 = 0.f;
  for (int j = j0; j < j1; j++) {
    int s = g_csrc[j];
    float e = g_as2[(tbase + s) * 4 + h] + adv;
    e = fmaxf(e, 0.2f * e);
    float w = expf(e - mx);
    sw += w;
    float wA = __shfl_sync(FULLMASK, w, hA);
    float wB = __shfl_sync(FULLMASK, w, hB);
    const float* hp = g_h2 + (tbase + s) * 64;
    acc0 = fmaf(wA, hp[lane], acc0);
    acc1 = fmaf(wB, hp[lane + 32], acc1);
  }
  float swA = __shfl_sync(FULLMASK, sw, hA);
  float swB = __shfl_sync(FULLMASK, sw, hB);
  float o0 = fmaxf(acc0 / (swA + 1e-16f) + b2[lane], 0.f) + pe_val(t, lane);
  float o1 = fmaxf(acc1 / (swB + 1e-16f) + b2[lane + 32], 0.f) + pe_val(t, lane + 32);
  g_seq[gw * 64 + lane] = o0;
  g_seq[gw * 64 + lane + 32] = o1;
}

// ================= shuffle-free dense kernels (64-row tiles, R=8 rows/warp) =================

// QKV: Y[row, 0..191] = X[row,:] @ Wqkv^T + bqkv.  dyn smem: Ws[64*193] + Xs[64*64]
__global__ __launch_bounds__(256) void k_qkv(const float* __restrict__ X,
                                             const float* __restrict__ W,
                                             const float* __restrict__ bias,
                                             float* __restrict__ Y) {
  extern __shared__ float sm[];
  float* Ws = sm;            // [i*193 + j], i<64, j<192 (padded stride kills conflicts)
  float* Xs = sm + 64 * 193; // [r*64 + i]
  for (int idx = threadIdx.x; idx < 192 * 64; idx += 256) {
    int j = idx >> 6, i = idx & 63;       // W row-major [192][64]
    Ws[i * 193 + j] = W[idx];
  }
  int row0 = blockIdx.x * 64;
  for (int idx = threadIdx.x; idx < 1024; idx += 256)
    ((float4*)Xs)[idx] = ((const float4*)(X + row0 * 64))[idx];
  __syncthreads();
  int lane = threadIdx.x & 31, warp = threadIdx.x >> 5;
  int r0 = warp * 8;
  float acc[8][6];
#pragma unroll
  for (int r = 0; r < 8; r++)
#pragma unroll
    for (int k = 0; k < 6; k++) acc[r][k] = 0.f;
#pragma unroll 4
  for (int i = 0; i < 64; i++) {
    float w[6];
#pragma unroll
    for (int k = 0; k < 6; k++) w[k] = Ws[i * 193 + lane + 32 * k];
#pragma unroll
    for (int r = 0; r < 8; r++) {
      float xv = Xs[(r0 + r) * 64 + i];
#pragma unroll
      for (int k = 0; k < 6; k++) acc[r][k] = fmaf(xv, w[k], acc[r][k]);
    }
  }
#pragma unroll
  for (int r = 0; r < 8; r++)
#pragma unroll
    for (int k = 0; k < 6; k++) {
      int j = lane + 32 * k;
      Y[(row0 + r0 + r) * 192 + j] = acc[r][k] + __ldg(&bias[j]);
    }
}

// O-proj + residual + LayerNorm (in place on seq). static smem 33KB.
__global__ __launch_bounds__(256) void k_oproj_ln(const float* __restrict__ O,
                                                  const float* __restrict__ W,
                                                  const float* __restrict__ bias,
                                                  const float* __restrict__ g,
                                                  const float* __restrict__ be,
                                                  float* __restrict__ seq) {
  __shared__ float Ws[64 * 65];  // [i*65 + j]
  __shared__ float Xs[64 * 64];
  for (int idx = threadIdx.x; idx < 64 * 64; idx += 256) {
    int j = idx >> 6, i = idx & 63;
    Ws[i * 65 + j] = W[idx];
  }
  int row0 = blockIdx.x * 64;
  for (int idx = threadIdx.x; idx < 1024; idx += 256)
    ((float4*)Xs)[idx] = ((const float4*)(O + row0 * 64))[idx];
  __syncthreads();
  int lane = threadIdx.x & 31, warp = threadIdx.x >> 5;
  int r0 = warp * 8;
  float a0[8], a1[8];
#pragma unroll
  for (int r = 0; r < 8; r++) { a0[r] = 0.f; a1[r] = 0.f; }
#pragma unroll 4
  for (int i = 0; i < 64; i++) {
    float w0 = Ws[i * 65 + lane];
    float w1 = Ws[i * 65 + lane + 32];
#pragma unroll
    for (int r = 0; r < 8; r++) {
      float xv = Xs[(r0 + r) * 64 + i];
      a0[r] = fmaf(xv, w0, a0[r]);
      a1[r] = fmaf(xv, w1, a1[r]);
    }
  }
  float b0 = __ldg(&bias[lane]), b1v = __ldg(&bias[lane + 32]);
  float g0 = __ldg(&g[lane]), g1v = __ldg(&g[lane + 32]);
  float e0 = __ldg(&be[lane]), e1 = __ldg(&be[lane + 32]);
#pragma unroll
  for (int r = 0; r < 8; r++) {
    int row = row0 + r0 + r;
    float y0 = a0[r] + b0 + seq[row * 64 + lane];
    float y1 = a1[r] + b1v + seq[row * 64 + lane + 32];
    float s = y0 + y1;
#pragma unroll
    for (int o = 16; o > 0; o >>= 1) s += __shfl_xor_sync(FULLMASK, s, o);
    float mu = s * (1.f / 64.f);
    float d0 = y0 - mu, d1 = y1 - mu;
    float v = d0 * d0 + d1 * d1;
#pragma unroll
    for (int o = 16; o > 0; o >>= 1) v += __shfl_xor_sync(FULLMASK, v, o);
    float rs = rsqrtf(v * (1.f / 64.f) + 1e-5f);
    seq[row * 64 + lane] = fmaf(d0 * rs, g0, e0);
    seq[row * 64 + lane + 32] = fmaf(d1 * rs, g1v, e1);
  }
}

// Fused FF: relu(X@Wf1^T+bf1)@Wf2^T+bf2 + residual + LN, in place on seq.
// dyn smem: W1s[64*129] + W2s[128*65] + Xs[64*64] + Ms[64*128]
__global__ __launch_bounds__(256) void k_ff(float* __restrict__ seq,
                                            const float* __restrict__ Wf1,
                                            const float* __restrict__ bf1,
                                            const float* __restrict__ Wf2,
                                            const float* __restrict__ bf2,
                                            const float* __restrict__ g,
                                            const float* __restrict__ be) {
  extern __shared__ float sm[];
  float* W1s = sm;                    // [i*129 + j], i<64, j<128
  float* W2s = W1s + 64 * 129;        // [i*65 + j], i<128, j<64
  float* Xs = W2s + 128 * 65;         // [r*64 + i]
  float* Ms = Xs + 64 * 64;           // [r*128 + j]
  for (int idx = threadIdx.x; idx < 128 * 64; idx += 256) {
    int j = idx >> 6, i = idx & 63;   // Wf1 [128][64]
    W1s[i * 129 + j] = Wf1[idx];
  }
  for (int idx = threadIdx.x; idx < 64 * 128; idx += 256) {
    int j = idx >> 7, i = idx & 127;  // Wf2 [64][128]
    W2s[i * 65 + j] = Wf2[idx];
  }
  int row0 = blockIdx.x * 64;
  for (int idx = threadIdx.x; idx < 1024; idx += 256)
    ((float4*)Xs)[idx] = ((const float4*)(seq + row0 * 64))[idx];
  __syncthreads();
  int lane = threadIdx.x & 31, warp = threadIdx.x >> 5;
  int r0 = warp * 8;
  // phase 1: mid = relu(X @ Wf1^T + bf1)
  {
    float acc[8][4];
#pragma unroll
    for (int r = 0; r < 8; r++)
#pragma unroll
      for (int k = 0; k < 4; k++) acc[r][k] = 0.f;
#pragma unroll 4
    for (int i = 0; i < 64; i++) {
      float w[4];
#pragma unroll
      for (int k = 0; k < 4; k++) w[k] = W1s[i * 129 + lane + 32 * k];
#pragma unroll
      for (int r = 0; r < 8; r++) {
        float xv = Xs[(r0 + r) * 64 + i];
#pragma unroll
        for (int k = 0; k < 4; k++) acc[r][k] = fmaf(xv, w[k], acc[r][k]);
      }
    }
#pragma unroll
    for (int r = 0; r < 8; r++)
#pragma unroll
      for (int k = 0; k < 4; k++) {
        int j = lane + 32 * k;
        Ms[(r0 + r) * 128 + j] = fmaxf(acc[r][k] + __ldg(&bf1[j]), 0.f);
      }
  }
  __syncthreads();
  // phase 2: out = mid @ Wf2^T + bf2 + X(residual), then LN
  float a0[8], a1[8];
#pragma unroll
  for (int r = 0; r < 8; r++) { a0[r] = 0.f; a1[r] = 0.f; }
#pragma unroll 4
  for (int i = 0; i < 128; i++) {
    float w0 = W2s[i * 65 + lane];
    float w1 = W2s[i * 65 + lane + 32];
#pragma unroll
    for (int r = 0; r < 8; r++) {
      float xv = Ms[(r0 + r) * 128 + i];
      a0[r] = fmaf(xv, w0, a0[r]);
      a1[r] = fmaf(xv, w1, a1[r]);
    }
  }
  float b0 = __ldg(&bf2[lane]), b1v = __ldg(&bf2[lane + 32]);
  float g0 = __ldg(&g[lane]), g1v = __ldg(&g[lane + 32]);
  float e0 = __ldg(&be[lane]), e1 = __ldg(&be[lane + 32]);
#pragma unroll
  for (int r = 0; r < 8; r++) {
    int rr = r0 + r;
    float y0 = a0[r] + b0 + Xs[rr * 64 + lane];
    float y1 = a1[r] + b1v + Xs[rr * 64 + lane + 32];
    float s = y0 + y1;
#pragma unroll
    for (int o = 16; o > 0; o >>= 1) s += __shfl_xor_sync(FULLMASK, s, o);
    float mu = s * (1.f / 64.f);
    float d0 = y0 - mu, d1 = y1 - mu;
    float v = d0 * d0 + d1 * d1;
#pragma unroll
    for (int o = 16; o > 0; o >>= 1) v += __shfl_xor_sync(FULLMASK, v, o);
    float rs = rsqrtf(v * (1.f / 64.f) + 1e-5f);
    int row = row0 + rr;
    seq[row * 64 + lane] = fmaf(d0 * rs, g0, e0);
    seq[row * 64 + lane + 32] = fmaf(d1 * rs, g1v, e1);
  }
}

// ---------------- attention over T=12 (per node, per head) ----------------
__global__ void k_attn() {
  __shared__ float ks[8][12][16];
  __shared__ float vs[8][12][16];
  int g = threadIdx.x / 12, tt = threadIdx.x - g * 12;
  int mh = blockIdx.x * 8 + g;
  int h = mh & 3, m = mh >> 2;
  const float* kp = g_qkv + (tt * Mc + m) * 192 + 64 + h * 16;
  const float* vp = kp + 64;
#pragma unroll
  for (int i = 0; i < 4; i++) {
    ((float4*)ks[g][tt])[i] = ((const float4*)kp)[i];
    ((float4*)vs[g][tt])[i] = ((const float4*)vp)[i];
  }
  float q[16];
  const float* qp = g_qkv + (tt * Mc + m) * 192 + h * 16;
#pragma unroll
  for (int i = 0; i < 4; i++) ((float4*)q)[i] = ((const float4*)qp)[i];
  __syncthreads();
  float sc[12];
  float mx = -1e30f;
#pragma unroll
  for (int s = 0; s < 12; s++) {
    float d = 0.f;
#pragma unroll
    for (int i = 0; i < 16; i++) d = fmaf(q[i], ks[g][s][i], d);
    d *= 0.25f;
    sc[s] = d; mx = fmaxf(mx, d);
  }
  float sum = 0.f;
#pragma unroll
  for (int s = 0; s < 12; s++) { sc[s] = expf(sc[s] - mx); sum += sc[s]; }
  float inv = 1.f / sum;
  float o[16];
#pragma unroll
  for (int i = 0; i < 16; i++) o[i] = 0.f;
#pragma unroll
  for (int s = 0; s < 12; s++) {
    float a = sc[s] * inv;
#pragma unroll
    for (int i = 0; i < 16; i++) o[i] = fmaf(a, vs[g][s][i], o[i]);
  }
  float* op = g_o + (tt * Mc + m) * 64 + h * 16;
#pragma unroll
  for (int i = 0; i < 4; i++) ((float4*)op)[i] = ((float4*)o)[i];
}

// ---------------- prediction head ----------------
__global__ void k_head(const float* __restrict__ Wh, const float* __restrict__ bh,
                       float* __restrict__ out) {
  int m = blockIdx.x * blockDim.x + threadIdx.x;
  if (m >= Mc) return;
  const float* sp = g_seq + ((Tc - 1) * Mc + m) * 64;
  float a0 = 0.f, a1 = 0.f, a2 = 0.f;
#pragma unroll 8
  for (int d = 0; d < 64; d++) {
    float v = sp[d];
    a0 = fmaf(v, __ldg(&Wh[d]), a0);
    a1 = fmaf(v, __ldg(&Wh[64 + d]), a1);
    a2 = fmaf(v, __ldg(&Wh[128 + d]), a2);
  }
  int b = m / Nc, n = m - b * Nc;
  out[(b * 3 + 0) * Nc + n] = a0 + __ldg(&bh[0]);
  out[(b * 3 + 1) * Nc + n] = a1 + __ldg(&bh[1]);
  out[(b * 3 + 2) * Nc + n] = a2 + __ldg(&bh[2]);
}

// ---------------- launch ----------------
extern "C" void kernel_launch(void* const* d_in, const int* in_sizes, int n_in,
                              void* d_out, int out_size) {
  const float* x    = (const float*)d_in[0];
  const int*   ei   = (const int*)d_in[1];
  const float* W1   = (const float*)d_in[2];
  const float* as1  = (const float*)d_in[3];
  const float* ad1  = (const float*)d_in[4];
  const float* b1   = (const float*)d_in[5];
  const float* W2   = (const float*)d_in[6];
  const float* as2w = (const float*)d_in[7];
  const float* ad2w = (const float*)d_in[8];
  const float* b2   = (const float*)d_in[9];
  const float* Wqkv = (const float*)d_in[10];
  const float* bqkv = (const float*)d_in[11];
  const float* Wo   = (const float*)d_in[12];
  const float* bo   = (const float*)d_in[13];
  const float* Wf1  = (const float*)d_in[14];
  const float* bf1  = (const float*)d_in[15];
  const float* Wf2  = (const float*)d_in[16];
  const float* bf2  = (const float*)d_in[17];
  const float* g1   = (const float*)d_in[18];
  const float* be1  = (const float*)d_in[19];
  const float* g2   = (const float*)d_in[20];
  const float* be2  = (const float*)d_in[21];
  const float* Wh   = (const float*)d_in[22];
  const float* bh   = (const float*)d_in[23];
  float* out = (float*)d_out;

  float *p_seq, *p_qkv, *p_o;
  cudaGetSymbolAddress((void**)&p_seq, g_seq);
  cudaGetSymbolAddress((void**)&p_qkv, g_qkv);
  cudaGetSymbolAddress((void**)&p_o, g_o);

  static bool attr_done = false;
  if (!attr_done) {
    cudaFuncSetAttribute(k_qkv, cudaFuncAttributeMaxDynamicSharedMemorySize,
                         (64 * 193 + 64 * 64) * 4);
    cudaFuncSetAttribute(k_ff, cudaFuncAttributeMaxDynamicSharedMemorySize,
                         (64 * 129 + 128 * 65 + 64 * 64 + 64 * 128) * 4);
    attr_done = true;
  }

  // graph CSR build
  k_init<<<(Mc + 255) / 256, 256>>>(W1, as1, ad1);
  k_hist<<<(ETOT + 255) / 256, 256>>>(ei);
  k_scan<<<1, 1024>>>();
  k_scatter<<<(ETOT + 255) / 256, 256>>>(ei);

  // GNN (all 12 timesteps batched)
  k_gat1<<<(ROWS + 255) / 256, 256>>>(x);
  k_gat2pre<<<(ROWS + 127) / 128, 128>>>(W1, b1, W2, as2w, ad2w);
  k_gat2agg<<<ROWS * 32 / 128, 128>>>(b2);

  // transformer encoder
  const int TB = ROWS / 64;  // 6000 blocks of 64 rows
  const int QKV_SMEM = (64 * 193 + 64 * 64) * 4;
  const int FF_SMEM = (64 * 129 + 128 * 65 + 64 * 64 + 64 * 128) * 4;
  for (int l = 0; l < Lc; l++) {
    k_qkv<<<TB, 256, QKV_SMEM>>>(p_seq, Wqkv + l * 192 * 64, bqkv + l * 192, p_qkv);
    k_attn<<<(Mc * NHc) / 8, 96>>>();
    k_oproj_ln<<<TB, 256>>>(p_o, Wo + l * 64 * 64, bo + l * 64,
                            g1 + l * 64, be1 + l * 64, p_seq);
    k_ff<<<TB, 256, FF_SMEM>>>(p_seq, Wf1 + l * 128 * 64, bf1 + l * 128,
                               Wf2 + l * 64 * 128, bf2 + l * 64,
                               g2 + l * 64, be2 + l * 64);
  }

  k_head<<<(Mc + 255) / 256, 256>>>(Wh, bh, out);
}